// round 11
// baseline (speedup 1.0000x reference)
#include <cuda_runtime.h>
#include <cstdint>
#include <cstddef>

// ---------------------------------------------------------------------------
// out = fq(x) @ fq(W)^T + bias, fq = per-tensor symmetric int8 fake quant.
// Exact: out = (q_x @ q_w^T) * (s_x*s_w) + bias, int32 accumulation.
//
// Hybrid GEMM: tensor-pipe CTAs (mma.sync; saturated at ~78 TOPS on sm_103,
// tcgen05 unavailable through this harness) + ALU/FMA-pipe CTAs (dp4a SIMT),
// co-resident per SM so both pipes run concurrently.
// R10: revert dp4a inner loop to R7 uint2 form (LDS.128 variant spilled:
// L2 5.7->14.9% regression, dp4a rate 3.96->3.37 cols/ms). Split from
// measured rates (r_dp4a=3.96, r_imma=9.28 cols/ms): DPT=9.
//   bx in [0,9):  dp4a path, columns [0,1152)
//   bx in [9,32): IMMA path, columns [1152,4096)
// ---------------------------------------------------------------------------

#define MT 16384
#define NT 4096
#define KT 4096

__device__ __align__(1024) int8_t g_qx[(size_t)MT * KT]; // 64 MiB scratch
__device__ __align__(1024) int8_t g_qw[(size_t)NT * KT]; // 16 MiB scratch
__device__ unsigned g_amax_x;
__device__ unsigned g_amax_w;

__device__ __forceinline__ uint32_t smem_to_u32(const void* smem_ptr) {
    uint32_t addr;
    asm("{ .reg .u64 tmp; cvta.to.shared.u64 tmp, %1; cvt.u32.u64 %0, tmp; }"
        : "=r"(addr) : "l"(smem_ptr));
    return addr;
}

// ---------------------------------------------------------------------------
// Pass 0: reset reduction state
// ---------------------------------------------------------------------------
__global__ void init_kernel() {
    if (threadIdx.x == 0) { g_amax_x = 0u; g_amax_w = 0u; }
}

// ---------------------------------------------------------------------------
// Pass 1 (fused): abs-max of x (blocks [0,XB)) and w (blocks [XB,XB+WB))
// ---------------------------------------------------------------------------
#define XB 2048
#define WB 512
__global__ void amax_fused_kernel(const float* __restrict__ x,
                                  const float* __restrict__ w) {
    __shared__ float red[8];
    int isw = (blockIdx.x >= XB);
    const float4* p4 = (const float4*)(isw ? w : x);
    int n4 = isw ? (NT * KT / 4) : (MT * KT / 4);
    int nb = isw ? WB : XB;
    int bid = isw ? (blockIdx.x - XB) : blockIdx.x;

    float m = 0.f;
    int stride = nb * blockDim.x;
    for (int i = bid * blockDim.x + threadIdx.x; i < n4; i += stride) {
        float4 v = p4[i];
        m = fmaxf(m, fmaxf(fmaxf(fabsf(v.x), fabsf(v.y)),
                           fmaxf(fabsf(v.z), fabsf(v.w))));
    }
    #pragma unroll
    for (int o = 16; o; o >>= 1) m = fmaxf(m, __shfl_xor_sync(0xffffffffu, m, o));
    if ((threadIdx.x & 31) == 0) red[threadIdx.x >> 5] = m;
    __syncthreads();
    if (threadIdx.x == 0) {
        float mm = red[0];
        for (int j = 1; j < (int)(blockDim.x >> 5); j++) mm = fmaxf(mm, red[j]);
        atomicMax(isw ? &g_amax_w : &g_amax_x, __float_as_uint(mm));
    }
}

// ---------------------------------------------------------------------------
// Pass 2 (fused): quantize x and w to int8
// ---------------------------------------------------------------------------
#define QXB 4096
#define QWB 1024
__device__ __forceinline__ int q1(float v, float inv_scale) {
    int q = __float2int_rn(v * inv_scale);   // round-half-even like jnp.round
    return max(-127, min(127, q));
}

__global__ void quant_fused_kernel(const float* __restrict__ x,
                                   const float* __restrict__ w) {
    int isw = (blockIdx.x >= QXB);
    float scale = fmaxf(__uint_as_float(isw ? g_amax_w : g_amax_x) * (1.f / 127.f),
                        1e-8f);
    float inv = 1.f / scale;
    const float4* in4 = (const float4*)(isw ? w : x);
    uint32_t* o4 = isw ? (uint32_t*)g_qw : (uint32_t*)g_qx;
    int n4 = isw ? (NT * KT / 4) : (MT * KT / 4);
    int nb = isw ? QWB : QXB;
    int bid = isw ? (blockIdx.x - QXB) : blockIdx.x;

    int stride = nb * blockDim.x;
    for (int i = bid * blockDim.x + threadIdx.x; i < n4; i += stride) {
        float4 v = in4[i];
        uint32_t u = (uint32_t)(q1(v.x, inv) & 0xff)
                   | ((uint32_t)(q1(v.y, inv) & 0xff) << 8)
                   | ((uint32_t)(q1(v.z, inv) & 0xff) << 16)
                   | ((uint32_t)(q1(v.w, inv) & 0xff) << 24);
        o4[i] = u;
    }
}

// ---------------------------------------------------------------------------
// Pass 3: hybrid GEMM, tile 128x128x128, 256 threads, 3-stage cp.async.
// ---------------------------------------------------------------------------
#define BM 128
#define BN 128
#define BK 128
#define STAGES 3
#define NITER (KT / BK)                  // 32
#define ASZ (BM * BK)                    // 16384 B
#define BSZ (BN * BK)                    // 16384 B
#define STAGE_BYTES (ASZ + BSZ)          // 32768 B
#define GEMM_SMEM (STAGES * STAGE_BYTES) // 98304 B
#define DPT 9                            // dp4a N-tiles (cols [0, 9*128))

// IMMA swizzle: 128B rows, chunk' = chunk ^ (row&7)
__device__ __forceinline__ uint32_t swz128(uint32_t row, uint32_t c) {
    return row * 128u + ((c ^ (row & 7u)) << 4);
}
// dp4a swizzle: chunk' = chunk ^ ((row ^ row>>3)&7)
__device__ __forceinline__ uint32_t swzdp(uint32_t row, uint32_t c) {
    return row * 128u + ((c ^ ((row ^ (row >> 3)) & 7u)) << 4);
}

#define CP16(dst, src) \
    asm volatile("cp.async.cg.shared.global [%0], [%1], 16;" :: "r"(dst), "l"(src))
#define CP_COMMIT() asm volatile("cp.async.commit_group;" ::: "memory")
#define CP_WAIT(n)  asm volatile("cp.async.wait_group %0;" :: "n"(n) : "memory")

#define LDSM_X4(r0, r1, r2, r3, a) \
    asm volatile("ldmatrix.sync.aligned.m8n8.x4.shared.b16 {%0,%1,%2,%3}, [%4];" \
        : "=r"(r0), "=r"(r1), "=r"(r2), "=r"(r3) : "r"(a))

#define MMA_S8(c, a, b0, b1) \
    asm volatile("mma.sync.aligned.m16n8k32.row.col.s32.s8.s8.s32 " \
        "{%0,%1,%2,%3}, {%4,%5,%6,%7}, {%8,%9}, {%0,%1,%2,%3};" \
        : "+r"((c)[0]), "+r"((c)[1]), "+r"((c)[2]), "+r"((c)[3]) \
        : "r"((a)[0]), "r"((a)[1]), "r"((a)[2]), "r"((a)[3]), "r"(b0), "r"(b1))

__global__ void __launch_bounds__(256, 2)
gemm_kernel(float* __restrict__ out, const float* __restrict__ bias) {
    extern __shared__ char smem[];
    uint32_t sb = smem_to_u32(smem);
    int tid = threadIdx.x, lane = tid & 31, w = tid >> 5;
    int mtile = blockIdx.y, bx = blockIdx.x;

    // Common cp.async thread mapping: rows {r0,+32,+64,+96}, 16B chunk cc.
    int r0 = tid >> 3, cc = tid & 7;
    const int8_t* gA = g_qx + ((size_t)(mtile * BM + r0)) * KT + cc * 16;
    const int8_t* gB = g_qw + ((size_t)(bx * BN + r0)) * KT + cc * 16;

    float sx = fmaxf(__uint_as_float(g_amax_x) * (1.f / 127.f), 1e-8f);
    float sw = fmaxf(__uint_as_float(g_amax_w) * (1.f / 127.f), 1e-8f);
    float sc = sx * sw;

    if (bx < DPT) {
        // ================= dp4a path (ALU/FMA pipes) =======================
        int ty = tid >> 4, tx = tid & 15;
        uint32_t tyk = (uint32_t)(ty & 7), txk = (uint32_t)(tx & 7);

        uint32_t dstA[4];
        #pragma unroll
        for (int it = 0; it < 4; it++)
            dstA[it] = swzdp((uint32_t)(r0 + 32 * it), (uint32_t)cc);

        int acc[8][8];
        #pragma unroll
        for (int i = 0; i < 8; i++)
            #pragma unroll
            for (int j = 0; j < 8; j++) acc[i][j] = 0;

        #pragma unroll
        for (int s = 0; s < STAGES - 1; s++) {
            uint32_t st = sb + (uint32_t)s * STAGE_BYTES;
            #pragma unroll
            for (int it = 0; it < 4; it++)
                CP16(st + dstA[it], gA + (size_t)it * 32 * KT + s * BK);
            #pragma unroll
            for (int it = 0; it < 4; it++)
                CP16(st + ASZ + dstA[it], gB + (size_t)it * 32 * KT + s * BK);
            CP_COMMIT();
        }

        for (int kc = 0; kc < NITER; kc++) {
            CP_WAIT(STAGES - 2);
            __syncthreads();

            int lc = kc + STAGES - 1;
            if (lc < NITER) {
                uint32_t st = sb + (uint32_t)(lc % STAGES) * STAGE_BYTES;
                #pragma unroll
                for (int it = 0; it < 4; it++)
                    CP16(st + dstA[it], gA + (size_t)it * 32 * KT + lc * BK);
                #pragma unroll
                for (int it = 0; it < 4; it++)
                    CP16(st + ASZ + dstA[it], gB + (size_t)it * 32 * KT + lc * BK);
            }
            CP_COMMIT();

            const char* base = smem + (size_t)(kc % STAGES) * STAGE_BYTES;

            // R7-proven inner loop: uint2 (LDS.64) fragment loads, no spills.
            #pragma unroll
            for (int c = 0; c < 8; c++) {
                uint32_t ao[8], bo[8];
                #pragma unroll
                for (int i = 0; i < 8; i++)
                    ao[i] = (uint32_t)((ty * 8 + i) * 128)
                          + (((uint32_t)c ^ ((uint32_t)i ^ tyk)) << 4);
                #pragma unroll
                for (int j = 0; j < 8; j++)
                    bo[j] = (uint32_t)((tx * 8 + j) * 128)
                          + (((uint32_t)c ^ ((uint32_t)j ^ txk)) << 4);

                #pragma unroll
                for (int h = 0; h < 2; h++) {
                    uint2 a2[8];
                    #pragma unroll
                    for (int i = 0; i < 8; i++)
                        a2[i] = *(const uint2*)(base + ao[i] + 8 * h);
                    #pragma unroll
                    for (int j = 0; j < 8; j++) {
                        uint2 b2 = *(const uint2*)(base + ASZ + bo[j] + 8 * h);
                        #pragma unroll
                        for (int i = 0; i < 8; i++) {
                            acc[i][j] = __dp4a((int)a2[i].x, (int)b2.x, acc[i][j]);
                            acc[i][j] = __dp4a((int)a2[i].y, (int)b2.y, acc[i][j]);
                        }
                    }
                }
            }
        }

        // epilogue
        int grow = mtile * BM + ty * 8;
        int gcol = bx * BN + tx * 8;
        float4 bv0 = *reinterpret_cast<const float4*>(bias + gcol);
        float4 bv1 = *reinterpret_cast<const float4*>(bias + gcol + 4);
        #pragma unroll
        for (int i = 0; i < 8; i++) {
            float* orow = out + (size_t)(grow + i) * NT + gcol;
            float4 v0, v1;
            v0.x = fmaf((float)acc[i][0], sc, bv0.x);
            v0.y = fmaf((float)acc[i][1], sc, bv0.y);
            v0.z = fmaf((float)acc[i][2], sc, bv0.z);
            v0.w = fmaf((float)acc[i][3], sc, bv0.w);
            v1.x = fmaf((float)acc[i][4], sc, bv1.x);
            v1.y = fmaf((float)acc[i][5], sc, bv1.y);
            v1.z = fmaf((float)acc[i][6], sc, bv1.z);
            v1.w = fmaf((float)acc[i][7], sc, bv1.w);
            *reinterpret_cast<float4*>(orow) = v0;
            *reinterpret_cast<float4*>(orow + 4) = v1;
        }
    } else {
        // ================= IMMA path (tensor pipe) =========================
        int wm = w & 1, wn = w >> 1;          // 2 x 4 warp grid
        uint32_t dA = swz128((uint32_t)r0, (uint32_t)cc);

        int acc[4][4][4];
        #pragma unroll
        for (int i = 0; i < 4; i++)
            #pragma unroll
            for (int j = 0; j < 4; j++)
                #pragma unroll
                for (int k = 0; k < 4; k++) acc[i][j][k] = 0;

        uint32_t a_row = (uint32_t)(wm * 64 + ((lane >> 3) & 1) * 8 + (lane & 7));
        uint32_t a_cb  = (uint32_t)((lane >> 4) & 1);
        uint32_t aoff[4];
        #pragma unroll
        for (int mt = 0; mt < 4; mt++) aoff[mt] = swz128(a_row + mt * 16, a_cb);

        uint32_t b_row = (uint32_t)(wn * 32 + ((lane >> 4) & 1) * 8 + (lane & 7));
        uint32_t b_cb  = (uint32_t)((lane >> 3) & 1);
        uint32_t boff[2];
        #pragma unroll
        for (int p = 0; p < 2; p++) boff[p] = swz128(b_row + p * 16, b_cb);

        #pragma unroll
        for (int s = 0; s < STAGES - 1; s++) {
            uint32_t st = sb + (uint32_t)s * STAGE_BYTES;
            #pragma unroll
            for (int it = 0; it < 4; it++)
                CP16(st + dA + it * 4096u, gA + (size_t)it * 32 * KT + s * BK);
            #pragma unroll
            for (int it = 0; it < 4; it++)
                CP16(st + ASZ + dA + it * 4096u, gB + (size_t)it * 32 * KT + s * BK);
            CP_COMMIT();
        }

        uint32_t afr[2][4][4], bfr[2][2][4];

        for (int kc = 0; kc < NITER; kc++) {
            CP_WAIT(STAGES - 2);
            __syncthreads();

            int lc = kc + STAGES - 1;
            if (lc < NITER) {
                uint32_t st = sb + (uint32_t)(lc % STAGES) * STAGE_BYTES;
                #pragma unroll
                for (int it = 0; it < 4; it++)
                    CP16(st + dA + it * 4096u, gA + (size_t)it * 32 * KT + lc * BK);
                #pragma unroll
                for (int it = 0; it < 4; it++)
                    CP16(st + ASZ + dA + it * 4096u,
                         gB + (size_t)it * 32 * KT + lc * BK);
            }
            CP_COMMIT();

            uint32_t sA = sb + (uint32_t)(kc % STAGES) * STAGE_BYTES;
            uint32_t sB = sA + ASZ;

            #pragma unroll
            for (int mt = 0; mt < 4; mt++)
                LDSM_X4(afr[0][mt][0], afr[0][mt][1], afr[0][mt][2], afr[0][mt][3],
                        sA + aoff[mt]);
            #pragma unroll
            for (int p = 0; p < 2; p++)
                LDSM_X4(bfr[0][p][0], bfr[0][p][1], bfr[0][p][2], bfr[0][p][3],
                        sB + boff[p]);

            #pragma unroll
            for (int ks = 0; ks < 4; ks++) {
                int cur = ks & 1, nxt = cur ^ 1;
                if (ks < 3) {
                    uint32_t x = (uint32_t)(ks + 1) << 5;
                    #pragma unroll
                    for (int mt = 0; mt < 4; mt++)
                        LDSM_X4(afr[nxt][mt][0], afr[nxt][mt][1],
                                afr[nxt][mt][2], afr[nxt][mt][3],
                                sA + (aoff[mt] ^ x));
                    #pragma unroll
                    for (int p = 0; p < 2; p++)
                        LDSM_X4(bfr[nxt][p][0], bfr[nxt][p][1],
                                bfr[nxt][p][2], bfr[nxt][p][3],
                                sB + (boff[p] ^ x));
                }
                #pragma unroll
                for (int mt = 0; mt < 4; mt++)
                    #pragma unroll
                    for (int nt = 0; nt < 4; nt++)
                        MMA_S8(acc[mt][nt], afr[cur][mt],
                               bfr[cur][nt >> 1][(nt & 1) * 2],
                               bfr[cur][nt >> 1][(nt & 1) * 2 + 1]);
            }
        }

        int colbase = bx * BN + wn * 32 + 2 * (lane & 3);
        int rowbase = mtile * BM + wm * 64 + (lane >> 2);

        float2 bv[4];
        #pragma unroll
        for (int nt = 0; nt < 4; nt++)
            bv[nt] = *reinterpret_cast<const float2*>(bias + colbase + nt * 8);

        #pragma unroll
        for (int mt = 0; mt < 4; mt++) {
            int r = rowbase + mt * 16;
            #pragma unroll
            for (int nt = 0; nt < 4; nt++) {
                int col = colbase + nt * 8;
                float2 v0, v1;
                v0.x = fmaf((float)acc[mt][nt][0], sc, bv[nt].x);
                v0.y = fmaf((float)acc[mt][nt][1], sc, bv[nt].y);
                v1.x = fmaf((float)acc[mt][nt][2], sc, bv[nt].x);
                v1.y = fmaf((float)acc[mt][nt][3], sc, bv[nt].y);
                *reinterpret_cast<float2*>(out + (size_t)r * NT + col) = v0;
                *reinterpret_cast<float2*>(out + (size_t)(r + 8) * NT + col) = v1;
            }
        }
    }
}

// ---------------------------------------------------------------------------
// Launch (graph-capturable; no allocation, no sync)
// ---------------------------------------------------------------------------
extern "C" void kernel_launch(void* const* d_in, const int* in_sizes, int n_in,
                              void* d_out, int out_size) {
    const float* x = (const float*)d_in[0];
    const float* w = (const float*)d_in[1];
    const float* bias = (const float*)d_in[2];
    float* out = (float*)d_out;

    init_kernel<<<1, 32>>>();
    amax_fused_kernel<<<XB + WB, 256>>>(x, w);
    quant_fused_kernel<<<QXB + QWB, 256>>>(x, w);

    cudaFuncSetAttribute(gemm_kernel,
                         cudaFuncAttributeMaxDynamicSharedMemorySize, GEMM_SMEM);
    gemm_kernel<<<dim3(NT / BN, MT / BM), 256, GEMM_SMEM>>>(out, bias);
}

// round 13
// speedup vs baseline: 1.0370x; 1.0370x over previous
#include <cuda_runtime.h>
#include <cstdint>
#include <cstddef>

// ---------------------------------------------------------------------------
// out = fq(x) @ fq(W)^T + bias, fq = per-tensor symmetric int8 fake quant.
// Exact: out = (q_x @ q_w^T) * (s_x*s_w) + bias, int32 accumulation.
//
// Hybrid GEMM: tensor-pipe CTAs (mma.sync, ~78 TOPS ceiling on sm_103;
// tcgen05 unavailable through this harness) + ALU-pipe CTAs (dp4a, ~68 TOPS
// ceiling at rt=2), co-resident per SM.
// R11: dp4a tiles shrunk to BN=64 so t_dp4a_CTA == t_imma_CTA (uniform CTA
// durations keep the scheduler's type mix stable -> both pipes fed all run).
// Split by measured rates (78:34): 20 x 64-wide dp4a + 22 x 128-wide IMMA.
//   bx in [0,20):  dp4a path, columns [0,1280), 64 cols/CTA
//   bx in [20,42): IMMA path, columns [1280,4096), 128 cols/CTA
// ---------------------------------------------------------------------------

#define MT 16384
#define NT 4096
#define KT 4096

__device__ __align__(1024) int8_t g_qx[(size_t)MT * KT]; // 64 MiB scratch
__device__ __align__(1024) int8_t g_qw[(size_t)NT * KT]; // 16 MiB scratch
__device__ unsigned g_amax_x;
__device__ unsigned g_amax_w;

__device__ __forceinline__ uint32_t smem_to_u32(const void* smem_ptr) {
    uint32_t addr;
    asm("{ .reg .u64 tmp; cvta.to.shared.u64 tmp, %1; cvt.u32.u64 %0, tmp; }"
        : "=r"(addr) : "l"(smem_ptr));
    return addr;
}

// ---------------------------------------------------------------------------
// Pass 0: reset reduction state
// ---------------------------------------------------------------------------
__global__ void init_kernel() {
    if (threadIdx.x == 0) { g_amax_x = 0u; g_amax_w = 0u; }
}

// ---------------------------------------------------------------------------
// Pass 1 (fused): abs-max of x (blocks [0,XB)) and w (blocks [XB,XB+WB))
// ---------------------------------------------------------------------------
#define XB 2048
#define WB 512
__global__ void amax_fused_kernel(const float* __restrict__ x,
                                  const float* __restrict__ w) {
    __shared__ float red[8];
    int isw = (blockIdx.x >= XB);
    const float4* p4 = (const float4*)(isw ? w : x);
    int n4 = isw ? (NT * KT / 4) : (MT * KT / 4);
    int nb = isw ? WB : XB;
    int bid = isw ? (blockIdx.x - XB) : blockIdx.x;

    float m = 0.f;
    int stride = nb * blockDim.x;
    for (int i = bid * blockDim.x + threadIdx.x; i < n4; i += stride) {
        float4 v = p4[i];
        m = fmaxf(m, fmaxf(fmaxf(fabsf(v.x), fabsf(v.y)),
                           fmaxf(fabsf(v.z), fabsf(v.w))));
    }
    #pragma unroll
    for (int o = 16; o; o >>= 1) m = fmaxf(m, __shfl_xor_sync(0xffffffffu, m, o));
    if ((threadIdx.x & 31) == 0) red[threadIdx.x >> 5] = m;
    __syncthreads();
    if (threadIdx.x == 0) {
        float mm = red[0];
        for (int j = 1; j < (int)(blockDim.x >> 5); j++) mm = fmaxf(mm, red[j]);
        atomicMax(isw ? &g_amax_w : &g_amax_x, __float_as_uint(mm));
    }
}

// ---------------------------------------------------------------------------
// Pass 2 (fused): quantize x and w to int8
// ---------------------------------------------------------------------------
#define QXB 4096
#define QWB 1024
__device__ __forceinline__ int q1(float v, float inv_scale) {
    int q = __float2int_rn(v * inv_scale);   // round-half-even like jnp.round
    return max(-127, min(127, q));
}

__global__ void quant_fused_kernel(const float* __restrict__ x,
                                   const float* __restrict__ w) {
    int isw = (blockIdx.x >= QXB);
    float scale = fmaxf(__uint_as_float(isw ? g_amax_w : g_amax_x) * (1.f / 127.f),
                        1e-8f);
    float inv = 1.f / scale;
    const float4* in4 = (const float4*)(isw ? w : x);
    uint32_t* o4 = isw ? (uint32_t*)g_qw : (uint32_t*)g_qx;
    int n4 = isw ? (NT * KT / 4) : (MT * KT / 4);
    int nb = isw ? QWB : QXB;
    int bid = isw ? (blockIdx.x - QXB) : blockIdx.x;

    int stride = nb * blockDim.x;
    for (int i = bid * blockDim.x + threadIdx.x; i < n4; i += stride) {
        float4 v = in4[i];
        uint32_t u = (uint32_t)(q1(v.x, inv) & 0xff)
                   | ((uint32_t)(q1(v.y, inv) & 0xff) << 8)
                   | ((uint32_t)(q1(v.z, inv) & 0xff) << 16)
                   | ((uint32_t)(q1(v.w, inv) & 0xff) << 24);
        o4[i] = u;
    }
}

// ---------------------------------------------------------------------------
// Pass 3: hybrid GEMM. IMMA tiles 128x128x128 (8 warps, mma.m16n8k32);
// dp4a tiles 128x64x128 (same duration as an IMMA CTA). 3-stage cp.async.
// ---------------------------------------------------------------------------
#define BM 128
#define BN 128
#define BND 64                           // dp4a tile N-width
#define BK 128
#define STAGES 3
#define NITER (KT / BK)                  // 32
#define ASZ (BM * BK)                    // 16384 B
#define BSZ (BN * BK)                    // 16384 B
#define BSZD (BND * BK)                  // 8192 B
#define STAGE_BYTES (ASZ + BSZ)          // 32768 B
#define GEMM_SMEM (STAGES * STAGE_BYTES) // 98304 B
#define DPN 20                           // dp4a tiles: cols [0, 20*64)
#define IMMA_COL0 (DPN * BND)            // 1280
#define GRIDX (DPN + (NT - IMMA_COL0) / BN)  // 20 + 22 = 42

// IMMA swizzle: 128B rows, chunk' = chunk ^ (row&7)
__device__ __forceinline__ uint32_t swz128(uint32_t row, uint32_t c) {
    return row * 128u + ((c ^ (row & 7u)) << 4);
}
// dp4a swizzle: chunk' = chunk ^ ((row ^ row>>3)&7)
__device__ __forceinline__ uint32_t swzdp(uint32_t row, uint32_t c) {
    return row * 128u + ((c ^ ((row ^ (row >> 3)) & 7u)) << 4);
}

#define CP16(dst, src) \
    asm volatile("cp.async.cg.shared.global [%0], [%1], 16;" :: "r"(dst), "l"(src))
#define CP_COMMIT() asm volatile("cp.async.commit_group;" ::: "memory")
#define CP_WAIT(n)  asm volatile("cp.async.wait_group %0;" :: "n"(n) : "memory")

#define LDSM_X4(r0, r1, r2, r3, a) \
    asm volatile("ldmatrix.sync.aligned.m8n8.x4.shared.b16 {%0,%1,%2,%3}, [%4];" \
        : "=r"(r0), "=r"(r1), "=r"(r2), "=r"(r3) : "r"(a))

#define MMA_S8(c, a, b0, b1) \
    asm volatile("mma.sync.aligned.m16n8k32.row.col.s32.s8.s8.s32 " \
        "{%0,%1,%2,%3}, {%4,%5,%6,%7}, {%8,%9}, {%0,%1,%2,%3};" \
        : "+r"((c)[0]), "+r"((c)[1]), "+r"((c)[2]), "+r"((c)[3]) \
        : "r"((a)[0]), "r"((a)[1]), "r"((a)[2]), "r"((a)[3]), "r"(b0), "r"(b1))

__global__ void __launch_bounds__(256, 2)
gemm_kernel(float* __restrict__ out, const float* __restrict__ bias) {
    extern __shared__ char smem[];
    uint32_t sb = smem_to_u32(smem);
    int tid = threadIdx.x, lane = tid & 31, w = tid >> 5;
    int mtile = blockIdx.y, bx = blockIdx.x;

    int r0 = tid >> 3, cc = tid & 7;     // loader mapping: row r0(+32k), chunk cc
    const int8_t* gA = g_qx + ((size_t)(mtile * BM + r0)) * KT + cc * 16;

    float sx = fmaxf(__uint_as_float(g_amax_x) * (1.f / 127.f), 1e-8f);
    float sw = fmaxf(__uint_as_float(g_amax_w) * (1.f / 127.f), 1e-8f);
    float sc = sx * sw;

    if (bx < DPN) {
        // ============ dp4a path (ALU/FMA pipes), tile 128x64 ===============
        const int8_t* gB = g_qw + ((size_t)(bx * BND + r0)) * KT + cc * 16;
        int ty = tid >> 4, tx = tid & 15;          // 16x16 thread grid
        uint32_t tyk = (uint32_t)(ty & 7);

        uint32_t dstA[4];
        #pragma unroll
        for (int it = 0; it < 4; it++)
            dstA[it] = swzdp((uint32_t)(r0 + 32 * it), (uint32_t)cc);

        int acc[8][4];                              // 8 rows x 4 cols
        #pragma unroll
        for (int i = 0; i < 8; i++)
            #pragma unroll
            for (int j = 0; j < 4; j++) acc[i][j] = 0;

        #pragma unroll
        for (int s = 0; s < STAGES - 1; s++) {
            uint32_t st = sb + (uint32_t)s * STAGE_BYTES;
            #pragma unroll
            for (int it = 0; it < 4; it++)
                CP16(st + dstA[it], gA + (size_t)it * 32 * KT + s * BK);
            #pragma unroll
            for (int it = 0; it < 2; it++)          // B: 64 rows only
                CP16(st + ASZ + dstA[it], gB + (size_t)it * 32 * KT + s * BK);
            CP_COMMIT();
        }

        for (int kc = 0; kc < NITER; kc++) {
            CP_WAIT(STAGES - 2);
            __syncthreads();

            int lc = kc + STAGES - 1;
            if (lc < NITER) {
                uint32_t st = sb + (uint32_t)(lc % STAGES) * STAGE_BYTES;
                #pragma unroll
                for (int it = 0; it < 4; it++)
                    CP16(st + dstA[it], gA + (size_t)it * 32 * KT + lc * BK);
                #pragma unroll
                for (int it = 0; it < 2; it++)
                    CP16(st + ASZ + dstA[it], gB + (size_t)it * 32 * KT + lc * BK);
            }
            CP_COMMIT();

            const char* base = smem + (size_t)(kc % STAGES) * STAGE_BYTES;

            #pragma unroll
            for (int c = 0; c < 8; c++) {
                uint32_t ao[8], bo[4];
                #pragma unroll
                for (int i = 0; i < 8; i++)
                    ao[i] = (uint32_t)((ty * 8 + i) * 128)
                          + (((uint32_t)c ^ ((uint32_t)i ^ tyk)) << 4);
                #pragma unroll
                for (int j = 0; j < 4; j++) {
                    uint32_t r = (uint32_t)(tx * 4 + j);
                    bo[j] = r * 128u
                          + (((uint32_t)c ^ ((r ^ (r >> 3)) & 7u)) << 4);
                }
                #pragma unroll
                for (int h = 0; h < 2; h++) {
                    uint2 a2[8];
                    #pragma unroll
                    for (int i = 0; i < 8; i++)
                        a2[i] = *(const uint2*)(base + ao[i] + 8 * h);
                    #pragma unroll
                    for (int j = 0; j < 4; j++) {
                        uint2 b2 = *(const uint2*)(base + ASZ + bo[j] + 8 * h);
                        #pragma unroll
                        for (int i = 0; i < 8; i++) {
                            acc[i][j] = __dp4a((int)a2[i].x, (int)b2.x, acc[i][j]);
                            acc[i][j] = __dp4a((int)a2[i].y, (int)b2.y, acc[i][j]);
                        }
                    }
                }
            }
        }

        // epilogue
        int grow = mtile * BM + ty * 8;
        int gcol = bx * BND + tx * 4;
        float4 bv = *reinterpret_cast<const float4*>(bias + gcol);
        #pragma unroll
        for (int i = 0; i < 8; i++) {
            float4 v;
            v.x = fmaf((float)acc[i][0], sc, bv.x);
            v.y = fmaf((float)acc[i][1], sc, bv.y);
            v.z = fmaf((float)acc[i][2], sc, bv.z);
            v.w = fmaf((float)acc[i][3], sc, bv.w);
            *reinterpret_cast<float4*>(out + (size_t)(grow + i) * NT + gcol) = v;
        }
    } else {
        // ============ IMMA path (tensor pipe), tile 128x128 ================
        int ncol0 = IMMA_COL0 + (bx - DPN) * BN;
        const int8_t* gB = g_qw + ((size_t)(ncol0 + r0)) * KT + cc * 16;
        int wm = w & 1, wn = w >> 1;          // 2 x 4 warp grid
        uint32_t dA = swz128((uint32_t)r0, (uint32_t)cc);

        int acc[4][4][4];
        #pragma unroll
        for (int i = 0; i < 4; i++)
            #pragma unroll
            for (int j = 0; j < 4; j++)
                #pragma unroll
                for (int k = 0; k < 4; k++) acc[i][j][k] = 0;

        uint32_t a_row = (uint32_t)(wm * 64 + ((lane >> 3) & 1) * 8 + (lane & 7));
        uint32_t a_cb  = (uint32_t)((lane >> 4) & 1);
        uint32_t aoff[4];
        #pragma unroll
        for (int mt = 0; mt < 4; mt++) aoff[mt] = swz128(a_row + mt * 16, a_cb);

        uint32_t b_row = (uint32_t)(wn * 32 + ((lane >> 4) & 1) * 8 + (lane & 7));
        uint32_t b_cb  = (uint32_t)((lane >> 3) & 1);
        uint32_t boff[2];
        #pragma unroll
        for (int p = 0; p < 2; p++) boff[p] = swz128(b_row + p * 16, b_cb);

        #pragma unroll
        for (int s = 0; s < STAGES - 1; s++) {
            uint32_t st = sb + (uint32_t)s * STAGE_BYTES;
            #pragma unroll
            for (int it = 0; it < 4; it++)
                CP16(st + dA + it * 4096u, gA + (size_t)it * 32 * KT + s * BK);
            #pragma unroll
            for (int it = 0; it < 4; it++)
                CP16(st + ASZ + dA + it * 4096u, gB + (size_t)it * 32 * KT + s * BK);
            CP_COMMIT();
        }

        uint32_t afr[2][4][4], bfr[2][2][4];

        for (int kc = 0; kc < NITER; kc++) {
            CP_WAIT(STAGES - 2);
            __syncthreads();

            int lc = kc + STAGES - 1;
            if (lc < NITER) {
                uint32_t st = sb + (uint32_t)(lc % STAGES) * STAGE_BYTES;
                #pragma unroll
                for (int it = 0; it < 4; it++)
                    CP16(st + dA + it * 4096u, gA + (size_t)it * 32 * KT + lc * BK);
                #pragma unroll
                for (int it = 0; it < 4; it++)
                    CP16(st + ASZ + dA + it * 4096u,
                         gB + (size_t)it * 32 * KT + lc * BK);
            }
            CP_COMMIT();

            uint32_t sA = sb + (uint32_t)(kc % STAGES) * STAGE_BYTES;
            uint32_t sB = sA + ASZ;

            #pragma unroll
            for (int mt = 0; mt < 4; mt++)
                LDSM_X4(afr[0][mt][0], afr[0][mt][1], afr[0][mt][2], afr[0][mt][3],
                        sA + aoff[mt]);
            #pragma unroll
            for (int p = 0; p < 2; p++)
                LDSM_X4(bfr[0][p][0], bfr[0][p][1], bfr[0][p][2], bfr[0][p][3],
                        sB + boff[p]);

            #pragma unroll
            for (int ks = 0; ks < 4; ks++) {
                int cur = ks & 1, nxt = cur ^ 1;
                if (ks < 3) {
                    uint32_t x = (uint32_t)(ks + 1) << 5;
                    #pragma unroll
                    for (int mt = 0; mt < 4; mt++)
                        LDSM_X4(afr[nxt][mt][0], afr[nxt][mt][1],
                                afr[nxt][mt][2], afr[nxt][mt][3],
                                sA + (aoff[mt] ^ x));
                    #pragma unroll
                    for (int p = 0; p < 2; p++)
                        LDSM_X4(bfr[nxt][p][0], bfr[nxt][p][1],
                                bfr[nxt][p][2], bfr[nxt][p][3],
                                sB + (boff[p] ^ x));
                }
                #pragma unroll
                for (int mt = 0; mt < 4; mt++)
                    #pragma unroll
                    for (int nt = 0; nt < 4; nt++)
                        MMA_S8(acc[mt][nt], afr[cur][mt],
                               bfr[cur][nt >> 1][(nt & 1) * 2],
                               bfr[cur][nt >> 1][(nt & 1) * 2 + 1]);
            }
        }

        int colbase = ncol0 + wn * 32 + 2 * (lane & 3);
        int rowbase = mtile * BM + wm * 64 + (lane >> 2);

        float2 bv[4];
        #pragma unroll
        for (int nt = 0; nt < 4; nt++)
            bv[nt] = *reinterpret_cast<const float2*>(bias + colbase + nt * 8);

        #pragma unroll
        for (int mt = 0; mt < 4; mt++) {
            int r = rowbase + mt * 16;
            #pragma unroll
            for (int nt = 0; nt < 4; nt++) {
                int col = colbase + nt * 8;
                float2 v0, v1;
                v0.x = fmaf((float)acc[mt][nt][0], sc, bv[nt].x);
                v0.y = fmaf((float)acc[mt][nt][1], sc, bv[nt].y);
                v1.x = fmaf((float)acc[mt][nt][2], sc, bv[nt].x);
                v1.y = fmaf((float)acc[mt][nt][3], sc, bv[nt].y);
                *reinterpret_cast<float2*>(out + (size_t)r * NT + col) = v0;
                *reinterpret_cast<float2*>(out + (size_t)(r + 8) * NT + col) = v1;
            }
        }
    }
}

// ---------------------------------------------------------------------------
// Launch (graph-capturable; no allocation, no sync)
// ---------------------------------------------------------------------------
extern "C" void kernel_launch(void* const* d_in, const int* in_sizes, int n_in,
                              void* d_out, int out_size) {
    const float* x = (const float*)d_in[0];
    const float* w = (const float*)d_in[1];
    const float* bias = (const float*)d_in[2];
    float* out = (float*)d_out;

    init_kernel<<<1, 32>>>();
    amax_fused_kernel<<<XB + WB, 256>>>(x, w);
    quant_fused_kernel<<<QXB + QWB, 256>>>(x, w);

    cudaFuncSetAttribute(gemm_kernel,
                         cudaFuncAttributeMaxDynamicSharedMemorySize, GEMM_SMEM);
    gemm_kernel<<<dim3(GRIDX, MT / BM), 256, GEMM_SMEM>>>(out, bias);
}